// round 15
// baseline (speedup 1.0000x reference)
#include <cuda_runtime.h>

// Mamba-2 SSD forward: b=16, s=1024, h=32, p=64, n=128, block_len=64.
// One CTA per (b,h), 512 threads. 16 chunks sequential, state S[128][64] in smem.
// Phase A: warps 0-7 GEMM1 (C*B^T -> Wt), warps 8-15 GEMM3 (Ct*S -> Y2).
// Phase B: all warps GEMM2 (Wt*X + Y2 -> gY) then GEMM4 (state update).
// All inner loops use packed fma.rn.f32x2.

#define CL    64
#define NDIM  128
#define PDIM  64
#define HNUM  32
#define SEQ   1024
#define NCHUNK 16
#define TPB   512

typedef unsigned long long u64;

__device__ __forceinline__ u64 pk2(float x, float y) {
    u64 r; asm("mov.b64 %0,{%1,%2};" : "=l"(r) : "f"(x), "f"(y)); return r;
}
__device__ __forceinline__ void upk2(u64 v, float& x, float& y) {
    asm("mov.b64 {%0,%1},%2;" : "=f"(x), "=f"(y) : "l"(v));
}
__device__ __forceinline__ u64 ffma2(u64 a, u64 b, u64 c) {
    u64 d; asm("fma.rn.f32x2 %0,%1,%2,%3;" : "=l"(d) : "l"(a), "l"(b), "l"(c)); return d;
}

struct __align__(16) Smem {
    float Ct[NDIM][68];    // C transposed: Ct[n][l]
    float Bt[NDIM][68];    // B transposed: Bt[n][l]
    float S [NDIM][68];    // state: S[n][p]
    float Bd[CL][132];     // B natural, pre-decayed: Bd[l][n]
    float X [CL][68];      // X natural: X[l][p]
    float Wt[CL][68];      // W transposed: Wt[s][l]  (also scan scratch in prologue)
    float Y2[CL][68];      // e[l] * (Ct*S)[l][p]
    float e_[NCHUNK][64];
    float einv_[NCHUNK][64];
    float dl_[NCHUNK][64];
};

__global__ __launch_bounds__(TPB, 1)
void ssd_kernel(const float* __restrict__ gX, const float* __restrict__ gA,
                const float* __restrict__ gB, const float* __restrict__ gC,
                float* __restrict__ gY)
{
    extern __shared__ Smem sm[];
    Smem& s = sm[0];

    const int tid  = threadIdx.x;
    const int lane = tid & 31;
    const int wid  = tid >> 5;
    const int bh   = blockIdx.x;
    const int bb   = bh >> 5;
    const int hh   = bh & 31;

    const int xbase = bb * SEQ * (HNUM * PDIM) + hh * PDIM;   // + row*2048
    const int bbase = bb * SEQ * (HNUM * NDIM) + hh * NDIM;   // + row*4096
    const int abase = bb * SEQ * HNUM + hh;

    // zero state
    for (int i = tid; i < NDIM * 68; i += TPB) (&s.S[0][0])[i] = 0.f;

    // ---------- prologue: per-chunk cumsum + exp factors for ALL 16 chunks ----------
    // Uses Wt[c][l] as scratch (512 threads cover 8 chunks per pass).
    #pragma unroll
    for (int pass = 0; pass < 2; ++pass) {
        const int c = (tid >> 6) + pass * 8;
        const int l = tid & 63;
        float a = gA[abase + (c * CL + l) * HNUM];
        #pragma unroll
        for (int o = 1; o < 32; o <<= 1) {
            float v = __shfl_up_sync(0xffffffffu, a, o);
            if (lane >= o) a += v;
        }
        s.Wt[c][l] = a;                 // warp-local inclusive scan
        __syncthreads();
        float base31 = s.Wt[c][31];
        if (l >= 32) a += base31;
        float last = s.Wt[c][63] + base31;
        s.e_[c][l]    = expf(a);
        s.einv_[c][l] = expf(-a);
        s.dl_[c][l]   = expf(last - a);
        __syncthreads();
    }

    for (int c = 0; c < NCHUNK; ++c) {
        const int srow0 = c * CL;

        // ---------- load chunk: X natural; B -> Bt + Bd(decayed); C -> Ct ----------
        #pragma unroll
        for (int k = 0; k < 2; ++k) {           // X: 1024 float4
            int idx = k * TPB + tid;
            int l   = idx >> 4;
            int c4  = (idx & 15) * 4;
            float4 v = *(const float4*)(gX + xbase + (srow0 + l) * 2048 + c4);
            *(float4*)&s.X[l][c4] = v;
        }
        #pragma unroll
        for (int k = 0; k < 4; ++k) {           // B: 2048 float4
            int idx = k * TPB + tid;
            int l   = idx & 63;
            int n0  = (idx >> 6) * 4;
            float4 v = *(const float4*)(gB + bbase + (srow0 + l) * 4096 + n0);
            s.Bt[n0 + 0][l] = v.x; s.Bt[n0 + 1][l] = v.y;
            s.Bt[n0 + 2][l] = v.z; s.Bt[n0 + 3][l] = v.w;
            float d = s.dl_[c][l];
            float4 vd = make_float4(v.x * d, v.y * d, v.z * d, v.w * d);
            *(float4*)&s.Bd[l][n0] = vd;
        }
        #pragma unroll
        for (int k = 0; k < 4; ++k) {           // C: 2048 float4
            int idx = k * TPB + tid;
            int l   = idx & 63;
            int n0  = (idx >> 6) * 4;
            float4 v = *(const float4*)(gC + bbase + (srow0 + l) * 4096 + n0);
            s.Ct[n0 + 0][l] = v.x; s.Ct[n0 + 1][l] = v.y;
            s.Ct[n0 + 2][l] = v.z; s.Ct[n0 + 3][l] = v.w;
        }
        __syncthreads();

        // ================= PHASE A =================
        if (tid < 256) {
            // ---- GEMM1: Wt[s][l] = mask(l>=s) * e[l]*einv[s] * sum_n Ct[n][l]*Bt[n][s]
            const int wy = wid >> 1, wx = wid & 1;
            const int l0 = wy * 16 + (lane >> 3) * 4;
            const int s0 = wx * 32 + (lane & 7) * 4;
            u64 acc[4][2] = {};
            if (l0 + 3 >= s0) {
                #pragma unroll 8
                for (int k = 0; k < NDIM; ++k) {
                    float4 av = *(const float4*)&s.Ct[k][l0];
                    const u64* bp = (const u64*)&s.Bt[k][s0];
                    u64 b0 = bp[0], b1 = bp[1];
                    float ar[4] = {av.x, av.y, av.z, av.w};
                    #pragma unroll
                    for (int i = 0; i < 4; ++i) {
                        u64 ai = pk2(ar[i], ar[i]);
                        acc[i][0] = ffma2(ai, b0, acc[i][0]);
                        acc[i][1] = ffma2(ai, b1, acc[i][1]);
                    }
                }
            }
            #pragma unroll
            for (int i = 0; i < 4; ++i) {
                float el = s.e_[c][l0 + i];
                float v[4];
                upk2(acc[i][0], v[0], v[1]);
                upk2(acc[i][1], v[2], v[3]);
                #pragma unroll
                for (int j = 0; j < 4; ++j) {
                    float w = (l0 + i >= s0 + j) ? v[j] * el * s.einv_[c][s0 + j] : 0.f;
                    s.Wt[s0 + j][l0 + i] = w;
                }
            }
        } else {
            // ---- GEMM3: Y2[l][p] = e[l] * sum_n Ct[n][l]*S[n][p]
            const int t2 = tid - 256;
            const int p0 = (t2 & 15) * 4;
            const int l0 = (t2 >> 4) * 4;
            u64 acc[4][2] = {};
            #pragma unroll 8
            for (int k = 0; k < NDIM; ++k) {
                float4 av = *(const float4*)&s.Ct[k][l0];
                const u64* bp = (const u64*)&s.S[k][p0];
                u64 b0 = bp[0], b1 = bp[1];
                float ar[4] = {av.x, av.y, av.z, av.w};
                #pragma unroll
                for (int i = 0; i < 4; ++i) {
                    u64 ai = pk2(ar[i], ar[i]);
                    acc[i][0] = ffma2(ai, b0, acc[i][0]);
                    acc[i][1] = ffma2(ai, b1, acc[i][1]);
                }
            }
            #pragma unroll
            for (int i = 0; i < 4; ++i) {
                float el = s.e_[c][l0 + i];
                float v[4];
                upk2(acc[i][0], v[0], v[1]);
                upk2(acc[i][1], v[2], v[3]);
                float4 y = make_float4(el * v[0], el * v[1], el * v[2], el * v[3]);
                *(float4*)&s.Y2[l0 + i][p0] = y;
            }
        }
        __syncthreads();

        // ================= PHASE B (all 16 warps) =================
        // ---- GEMM2: Y[l][p] = sum_s Wt[s][l]*X[s][p] + Y2[l][p]   (4l x 2p per thread)
        {
            const int p0 = (tid & 31) * 2;
            const int l0 = (tid >> 5) * 4;
            u64 acc[4] = {};
            #pragma unroll 8
            for (int k = 0; k < CL; ++k) {
                float4 av = *(const float4*)&s.Wt[k][l0];   // warp-broadcast
                u64 b = *(const u64*)&s.X[k][p0];
                float ar[4] = {av.x, av.y, av.z, av.w};
                #pragma unroll
                for (int i = 0; i < 4; ++i)
                    acc[i] = ffma2(pk2(ar[i], ar[i]), b, acc[i]);
            }
            #pragma unroll
            for (int i = 0; i < 4; ++i) {
                float y0, y1;
                upk2(acc[i], y0, y1);
                y0 += s.Y2[l0 + i][p0];
                y1 += s.Y2[l0 + i][p0 + 1];
                float2 y = make_float2(y0, y1);
                *(float2*)(gY + xbase + (srow0 + l0 + i) * 2048 + p0) = y;
            }
        }
        // ---- GEMM4: S[n][p] = e[63]*S[n][p] + sum_l Bd[l][n]*X[l][p]   (4n x 4p per thread)
        {
            const int p0 = (tid & 15) * 4;
            const int n0 = (tid >> 4) * 4;
            const float E = s.e_[c][CL - 1];
            u64 acc[4][2];
            #pragma unroll
            for (int r = 0; r < 4; ++r) {
                float4 v = *(const float4*)&s.S[n0 + r][p0];
                acc[r][0] = pk2(v.x * E, v.y * E);
                acc[r][1] = pk2(v.z * E, v.w * E);
            }
            #pragma unroll 8
            for (int k = 0; k < CL; ++k) {
                const u64* bp = (const u64*)&s.X[k][p0];
                u64 b0 = bp[0], b1 = bp[1];
                float4 a = *(const float4*)&s.Bd[k][n0];
                float ar[4] = {a.x, a.y, a.z, a.w};
                #pragma unroll
                for (int r = 0; r < 4; ++r) {
                    u64 ai = pk2(ar[r], ar[r]);
                    acc[r][0] = ffma2(ai, b0, acc[r][0]);
                    acc[r][1] = ffma2(ai, b1, acc[r][1]);
                }
            }
            #pragma unroll
            for (int r = 0; r < 4; ++r) {
                float v[4];
                upk2(acc[r][0], v[0], v[1]);
                upk2(acc[r][1], v[2], v[3]);
                *(float4*)&s.S[n0 + r][p0] = make_float4(v[0], v[1], v[2], v[3]);
            }
        }
        __syncthreads();   // protect S/X/Bt/Bd/Ct/Wt/Y2 before next chunk
    }
}

extern "C" void kernel_launch(void* const* d_in, const int* in_sizes, int n_in,
                              void* d_out, int out_size)
{
    const float* X = (const float*)d_in[0];
    const float* A = (const float*)d_in[1];
    const float* B = (const float*)d_in[2];
    const float* C = (const float*)d_in[3];
    float*       Y = (float*)d_out;

    cudaFuncSetAttribute(ssd_kernel,
                         cudaFuncAttributeMaxDynamicSharedMemorySize,
                         (int)sizeof(Smem));
    ssd_kernel<<<16 * HNUM, TPB, sizeof(Smem)>>>(X, A, B, C, Y);
}

// round 16
// speedup vs baseline: 1.2493x; 1.2493x over previous
#include <cuda_runtime.h>

// Mamba-2 SSD forward: b=16, s=1024, h=32, p=64, n=128, block_len=64.
// One CTA per (b,h), 256 threads. 16 chunks sequential; state S[128][64] in smem.
// Phase A (all threads): fused GEMM1 (C*B^T -> Wt, masked/decayed) + GEMM3
//   (Ct*S -> Y_off) sharing Ct loads; Y_off kept in registers.
// Phase B (all threads): fused GEMM2 (Wt*X + Y_off -> gY) + GEMM4 (state update)
//   sharing X loads. All inner loops use packed fma.rn.f32x2.

#define CL    64
#define NDIM  128
#define PDIM  64
#define HNUM  32
#define SEQ   1024
#define NCHUNK 16
#define TPB   256

typedef unsigned long long u64;

__device__ __forceinline__ u64 pk2(float x, float y) {
    u64 r; asm("mov.b64 %0,{%1,%2};" : "=l"(r) : "f"(x), "f"(y)); return r;
}
__device__ __forceinline__ void upk2(u64 v, float& x, float& y) {
    asm("mov.b64 {%0,%1},%2;" : "=f"(x), "=f"(y) : "l"(v));
}
__device__ __forceinline__ u64 ffma2(u64 a, u64 b, u64 c) {
    u64 d; asm("fma.rn.f32x2 %0,%1,%2,%3;" : "=l"(d) : "l"(a), "l"(b), "l"(c)); return d;
}

// Bd in-row swizzle: 4 pad words after every 32 data words (kills the
// stride-8-word 4-way bank conflict on 8-wide n-tile loads).
#define BDW(n) ((n) + 4 * ((n) >> 5))
#define BDROW  144

struct __align__(16) Smem {
    float Ct[NDIM][68];    // C transposed: Ct[n][l]
    float Bt[NDIM][68];    // B transposed: Bt[n][l]
    float S [NDIM][68];    // state: S[n][p]
    float Bd[CL][BDROW];   // B natural, pre-decayed, in-row padded
    float X [CL][68];      // X natural: X[l][p]
    float Wt[CL][68];      // W transposed: Wt[s][l] (scan scratch in prologue)
    float e_[NCHUNK][64];
    float einv_[NCHUNK][64];
    float dl_[NCHUNK][64];
};

__global__ __launch_bounds__(TPB, 1)
void ssd_kernel(const float* __restrict__ gX, const float* __restrict__ gA,
                const float* __restrict__ gB, const float* __restrict__ gC,
                float* __restrict__ gY)
{
    extern __shared__ Smem sm[];
    Smem& s = sm[0];

    const int tid  = threadIdx.x;
    const int lane = tid & 31;
    const int bh   = blockIdx.x;
    const int bb   = bh >> 5;
    const int hh   = bh & 31;

    const int xbase = bb * SEQ * (HNUM * PDIM) + hh * PDIM;   // + row*2048
    const int bbase = bb * SEQ * (HNUM * NDIM) + hh * NDIM;   // + row*4096
    const int abase = bb * SEQ * HNUM + hh;

    // zero state
    for (int i = tid; i < NDIM * 68; i += TPB) (&s.S[0][0])[i] = 0.f;

    // ---------- prologue: cumsum + exp factors for ALL 16 chunks ----------
    #pragma unroll
    for (int pass = 0; pass < 4; ++pass) {
        const int cc = (tid >> 6) + pass * 4;
        const int l  = tid & 63;
        float a = gA[abase + (cc * CL + l) * HNUM];
        #pragma unroll
        for (int o = 1; o < 32; o <<= 1) {
            float v = __shfl_up_sync(0xffffffffu, a, o);
            if (lane >= o) a += v;
        }
        s.Wt[cc][l] = a;                 // warp-local inclusive scan
        __syncthreads();
        float base31 = s.Wt[cc][31];
        if (l >= 32) a += base31;
        float last = s.Wt[cc][63] + base31;
        s.e_[cc][l]    = expf(a);
        s.einv_[cc][l] = expf(-a);
        s.dl_[cc][l]   = expf(last - a);
        __syncthreads();
    }

    const int l0  = (tid >> 4) * 4;     // 4 l-rows  (also used for Wt reads)
    const int sp0 = (tid & 15) * 4;     // 4 s-cols == 4 p-cols
    const int n0  = (tid >> 4) * 8;     // 8 n-rows for state update
    const int bdw0 = BDW(n0);

    for (int c = 0; c < NCHUNK; ++c) {
        const int srow0 = c * CL;

        // ---------- load chunk: X natural; B -> Bt + Bd(decayed); C -> Ct ----------
        #pragma unroll
        for (int k = 0; k < 4; ++k) {           // X: 1024 float4
            int idx = k * TPB + tid;
            int l   = idx >> 4;
            int c4  = (idx & 15) * 4;
            float4 v = *(const float4*)(gX + xbase + (srow0 + l) * 2048 + c4);
            *(float4*)&s.X[l][c4] = v;
        }
        #pragma unroll
        for (int k = 0; k < 8; ++k) {           // B: 2048 float4
            int idx = k * TPB + tid;
            int l   = idx & 63;
            int nn  = (idx >> 6) * 4;
            float4 v = *(const float4*)(gB + bbase + (srow0 + l) * 4096 + nn);
            s.Bt[nn + 0][l] = v.x; s.Bt[nn + 1][l] = v.y;
            s.Bt[nn + 2][l] = v.z; s.Bt[nn + 3][l] = v.w;
            float d = s.dl_[c][l];
            float4 vd = make_float4(v.x * d, v.y * d, v.z * d, v.w * d);
            *(float4*)&s.Bd[l][BDW(nn)] = vd;
        }
        #pragma unroll
        for (int k = 0; k < 8; ++k) {           // C: 2048 float4
            int idx = k * TPB + tid;
            int l   = idx & 63;
            int nn  = (idx >> 6) * 4;
            float4 v = *(const float4*)(gC + bbase + (srow0 + l) * 4096 + nn);
            s.Ct[nn + 0][l] = v.x; s.Ct[nn + 1][l] = v.y;
            s.Ct[nn + 2][l] = v.z; s.Ct[nn + 3][l] = v.w;
        }
        __syncthreads();

        // ================= PHASE A: fused GEMM1 + GEMM3 (shared Ct) =================
        float y2[4][4];
        {
            u64 accW[4][2] = {};
            u64 accY[4][2] = {};
            #pragma unroll 8
            for (int k = 0; k < NDIM; ++k) {
                float4 av = *(const float4*)&s.Ct[k][l0];     // warp-broadcast (2 uniq)
                const u64* bp = (const u64*)&s.Bt[k][sp0];
                u64 b0 = bp[0], b1 = bp[1];
                const u64* cp = (const u64*)&s.S[k][sp0];
                u64 c0 = cp[0], c1 = cp[1];
                float ar[4] = {av.x, av.y, av.z, av.w};
                #pragma unroll
                for (int i = 0; i < 4; ++i) {
                    u64 ai = pk2(ar[i], ar[i]);
                    accW[i][0] = ffma2(ai, b0, accW[i][0]);
                    accW[i][1] = ffma2(ai, b1, accW[i][1]);
                    accY[i][0] = ffma2(ai, c0, accY[i][0]);
                    accY[i][1] = ffma2(ai, c1, accY[i][1]);
                }
            }
            #pragma unroll
            for (int i = 0; i < 4; ++i) {
                float el = s.e_[c][l0 + i];
                float w[4], v[4];
                upk2(accW[i][0], w[0], w[1]);
                upk2(accW[i][1], w[2], w[3]);
                upk2(accY[i][0], v[0], v[1]);
                upk2(accY[i][1], v[2], v[3]);
                #pragma unroll
                for (int j = 0; j < 4; ++j) {
                    float wm = (l0 + i >= sp0 + j) ? w[j] * el * s.einv_[c][sp0 + j] : 0.f;
                    s.Wt[sp0 + j][l0 + i] = wm;
                    y2[i][j] = el * v[j];
                }
            }
        }
        __syncthreads();

        // ================= PHASE B: fused GEMM2 + GEMM4 (shared X) =================
        {
            u64 accO[4][2];
            #pragma unroll
            for (int i = 0; i < 4; ++i) {
                accO[i][0] = pk2(y2[i][0], y2[i][1]);
                accO[i][1] = pk2(y2[i][2], y2[i][3]);
            }
            const float E = s.e_[c][CL - 1];
            u64 accS[8][2];
            #pragma unroll
            for (int r = 0; r < 8; ++r) {
                float4 v = *(const float4*)&s.S[n0 + r][sp0];
                accS[r][0] = pk2(v.x * E, v.y * E);
                accS[r][1] = pk2(v.z * E, v.w * E);
            }
            #pragma unroll 8
            for (int k = 0; k < CL; ++k) {
                const u64* xp = (const u64*)&s.X[k][sp0];
                u64 x0 = xp[0], x1 = xp[1];
                float4 wv = *(const float4*)&s.Wt[k][l0];     // warp-broadcast
                float wr[4] = {wv.x, wv.y, wv.z, wv.w};
                #pragma unroll
                for (int i = 0; i < 4; ++i) {
                    u64 ai = pk2(wr[i], wr[i]);
                    accO[i][0] = ffma2(ai, x0, accO[i][0]);
                    accO[i][1] = ffma2(ai, x1, accO[i][1]);
                }
                float4 g0 = *(const float4*)&s.Bd[k][bdw0];
                float4 g1 = *(const float4*)&s.Bd[k][bdw0 + 4];
                float gr[8] = {g0.x, g0.y, g0.z, g0.w, g1.x, g1.y, g1.z, g1.w};
                #pragma unroll
                for (int r = 0; r < 8; ++r) {
                    u64 ai = pk2(gr[r], gr[r]);
                    accS[r][0] = ffma2(ai, x0, accS[r][0]);
                    accS[r][1] = ffma2(ai, x1, accS[r][1]);
                }
            }
            #pragma unroll
            for (int i = 0; i < 4; ++i) {
                float y[4];
                upk2(accO[i][0], y[0], y[1]);
                upk2(accO[i][1], y[2], y[3]);
                *(float4*)(gY + xbase + (srow0 + l0 + i) * 2048 + sp0) =
                    make_float4(y[0], y[1], y[2], y[3]);
            }
            #pragma unroll
            for (int r = 0; r < 8; ++r) {
                float v[4];
                upk2(accS[r][0], v[0], v[1]);
                upk2(accS[r][1], v[2], v[3]);
                *(float4*)&s.S[n0 + r][sp0] = make_float4(v[0], v[1], v[2], v[3]);
            }
        }
        __syncthreads();   // protect S/X/Bt/Bd/Ct/Wt before next chunk's loads
    }
}

extern "C" void kernel_launch(void* const* d_in, const int* in_sizes, int n_in,
                              void* d_out, int out_size)
{
    const float* X = (const float*)d_in[0];
    const float* A = (const float*)d_in[1];
    const float* B = (const float*)d_in[2];
    const float* C = (const float*)d_in[3];
    float*       Y = (float*)d_out;

    cudaFuncSetAttribute(ssd_kernel,
                         cudaFuncAttributeMaxDynamicSharedMemorySize,
                         (int)sizeof(Smem));
    ssd_kernel<<<16 * HNUM, TPB, sizeof(Smem)>>>(X, A, B, C, Y);
}